// round 6
// baseline (speedup 1.0000x reference)
#include <cuda_runtime.h>
#include <cuda_fp16.h>

#define BATCH 8
#define LEN   2048
#define EMB   512
#define NQ    8
#define IT    8      // i-rows per attn block
#define JPT   4      // j-columns per thread

// scratch for rot = x @ rotation : (8, 2048, 8) fp32 = 512 KB (L2-resident)
__device__ float g_rot[BATCH * LEN * NQ];

__device__ __forceinline__ float tanh_fast(float x) {
    float y;
    asm("tanh.approx.f32 %0, %1;" : "=f"(y) : "f"(x));
    return y;
}

// ---------------------------------------------------------------------------
// Kernel 1: rot[b,l,q] = sum_e x[b,l,e] * rotation[e,q]
// 1024 blocks x 256 threads. Each warp computes 2 rows; all 8 row-loads
// (LDG.128, streaming .cs — x is read-once) issued up-front (MLP=8).
// Swap-butterfly reduction (16 SHFL), lanes 0..15 store coalesced.
// ---------------------------------------------------------------------------
__global__ __launch_bounds__(256) void rot_kernel(const float* __restrict__ x,
                                                  const float* __restrict__ rotation)
{
    __shared__ float4 srotT4[NQ][EMB / 4];   // transposed rotation, 16 KB
    const int tid = threadIdx.x;

    float* srot = reinterpret_cast<float*>(srotT4);
    for (int idx = tid; idx < EMB * NQ; idx += 256) {
        int e = idx >> 3;
        int q = idx & 7;
        srot[q * EMB + e] = rotation[idx];
    }
    __syncthreads();

    const int warp = tid >> 5;
    const int lane = tid & 31;
    const int row0 = (blockIdx.x * 8 + warp) * 2;   // 2 rows per warp

    // issue all 8 global loads first (2 rows x 4 chunks), MLP = 8, streaming
    float4 xv[2][4];
#pragma unroll
    for (int r = 0; r < 2; r++)
#pragma unroll
        for (int k = 0; k < 4; k++)
            xv[r][k] = __ldcs(reinterpret_cast<const float4*>(
                x + (size_t)(row0 + r) * EMB) + k * 32 + lane);

    float a[16];   // a[o], o = r*8+q
#pragma unroll
    for (int o = 0; o < 16; o++) a[o] = 0.0f;

#pragma unroll
    for (int k = 0; k < 4; k++) {
#pragma unroll
        for (int q = 0; q < NQ; q++) {
            const float4 rq = srotT4[q][k * 32 + lane];
#pragma unroll
            for (int r = 0; r < 2; r++) {
                float& acc = a[r * 8 + q];
                acc = fmaf(xv[r][k].x, rq.x, acc);
                acc = fmaf(xv[r][k].y, rq.y, acc);
                acc = fmaf(xv[r][k].z, rq.z, acc);
                acc = fmaf(xv[r][k].w, rq.w, acc);
            }
        }
    }

    // swap-butterfly reduce; after stages 8,4,2,1 lane l holds acc[l&15]
    // summed over its 16-lane half; one extra stage merges the halves.
#pragma unroll
    for (int off = 8; off >= 1; off >>= 1) {
#pragma unroll
        for (int t = 0; t < 8; t++) {
            if (t < off) {
                const bool hi = (lane & off) != 0;
                const float give = hi ? a[t] : a[t + off];
                const float keep = hi ? a[t + off] : a[t];
                a[t] = keep + __shfl_xor_sync(0xffffffffu, give, off);
            }
        }
    }
    a[0] += __shfl_xor_sync(0xffffffffu, a[0], 16);

    if (lane < 16)
        g_rot[(size_t)row0 * NQ + lane] = a[0];
}

// ---------------------------------------------------------------------------
// Kernel 2: scores[b,i,j] = sigmoid(rot_i . rot_j) / row_sum
//   sigmoid(s) = 0.5 + 0.5*tanh(0.5*s)   (0.5 folded into qi)
//   row_sum    = 1024 + 0.5*sum_j tanh   ->  out = fmaf(t, h, h), h = 0.5/row_sum
// Block = 512 threads (16 warps), IT=8 i-rows, JPT=4 j per thread,
// grid (256, 8) = 2048 blocks, 2 blocks/SM (barrier phases overlap).
// tanh values held as half2 (exact at the +-1 saturation that dominates);
// row sums accumulated in fp32. Stores are STG.128 streaming.
// ---------------------------------------------------------------------------
__global__ __launch_bounds__(512, 2) void attn_kernel(float* __restrict__ out)
{
    const int b    = blockIdx.y;
    const int i0   = blockIdx.x * IT;
    const int tid  = threadIdx.x;
    const int warp = tid >> 5;
    const int lane = tid & 31;

    __shared__ float s_q[IT * NQ];     // 0.5 * qi rows, 64 floats
    __shared__ float s_part[IT][16];
    __shared__ float s_h[IT];

    if (tid < IT * NQ)
        s_q[tid] = 0.5f * g_rot[((size_t)b * LEN + i0) * NQ + tid];

    // this thread's 4 j-rows (128B contiguous): 8 x LDG.128, MLP = 8
    const float4* rj = reinterpret_cast<const float4*>(
        &g_rot[((size_t)b * LEN + tid * JPT) * NQ]);
    float4 v0[JPT], v1[JPT];
#pragma unroll
    for (int r = 0; r < JPT; r++) {
        v0[r] = __ldg(rj + r * 2 + 0);
        v1[r] = __ldg(rj + r * 2 + 1);
    }

    __syncthreads();

    __half2 th[IT][2];      // tanh values, pairs (t0,t1) (t2,t3)
    float   a[IT];          // fp32 partial row sums
    const float4* sq4 = reinterpret_cast<const float4*>(s_q);

#pragma unroll
    for (int i = 0; i < IT; i++) {
        const float4 q0 = sq4[i * 2 + 0];   // broadcast LDS.128
        const float4 q1 = sq4[i * 2 + 1];
        float t[JPT];
#pragma unroll
        for (int r = 0; r < JPT; r++) {
            float s0 = v0[r].x * q0.x;
            float s1 = v1[r].x * q1.x;
            s0 = fmaf(v0[r].y, q0.y, s0);
            s1 = fmaf(v1[r].y, q1.y, s1);
            s0 = fmaf(v0[r].z, q0.z, s0);
            s1 = fmaf(v1[r].z, q1.z, s1);
            s0 = fmaf(v0[r].w, q0.w, s0);
            s1 = fmaf(v1[r].w, q1.w, s1);
            t[r] = tanh_fast(s0 + s1);
        }
        a[i] = (t[0] + t[1]) + (t[2] + t[3]);
        th[i][0] = __floats2half2_rn(t[0], t[1]);
        th[i][1] = __floats2half2_rn(t[2], t[3]);
    }

    // swap-butterfly warp reduce of 8 row partials: stages 4,2,1 then 8,16.
    // After: every lane holds this warp's partial for row (lane & 7).
#pragma unroll
    for (int off = 4; off >= 1; off >>= 1) {
#pragma unroll
        for (int t = 0; t < 4; t++) {
            if (t < off) {
                const bool hi = (lane & off) != 0;
                const float give = hi ? a[t] : a[t + off];
                const float keep = hi ? a[t + off] : a[t];
                a[t] = keep + __shfl_xor_sync(0xffffffffu, give, off);
            }
        }
    }
    a[0] += __shfl_xor_sync(0xffffffffu, a[0], 8);
    a[0] += __shfl_xor_sync(0xffffffffu, a[0], 16);

    if (lane < IT)
        s_part[lane][warp] = a[0];

    __syncthreads();

    // second level: warp i (<8) reduces row i's 16 warp-partials
    if (warp < IT) {
        float p = (lane < 16) ? s_part[warp][lane] : 0.0f;
#pragma unroll
        for (int off = 8; off >= 1; off >>= 1)
            p += __shfl_xor_sync(0xffffffffu, p, off);
        if (lane == 0)
            s_h[warp] = __fdividef(0.5f, fmaf(0.5f, p, 1024.0f));
    }
    __syncthreads();

    float4* obase = reinterpret_cast<float4*>(
        out + ((size_t)(b * LEN + i0)) * LEN) + tid;
#pragma unroll
    for (int i = 0; i < IT; i++) {
        const float h = s_h[i];
        const float2 lo = __half22float2(th[i][0]);
        const float2 hi = __half22float2(th[i][1]);
        float4 o;
        o.x = fmaf(lo.x, h, h);
        o.y = fmaf(lo.y, h, h);
        o.z = fmaf(hi.x, h, h);
        o.w = fmaf(hi.y, h, h);
        __stcs(obase, o);                 // evict-first streaming STG.128
        obase += LEN / 4;
    }
}

extern "C" void kernel_launch(void* const* d_in, const int* in_sizes, int n_in,
                              void* d_out, int out_size)
{
    const float* x        = (const float*)d_in[0];   // (8, 2048, 512)
    const float* rotation = (const float*)d_in[1];   // (512, 8)
    float* out = (float*)d_out;                      // (8, 2048, 2048)

    rot_kernel<<<1024, 256>>>(x, rotation);

    dim3 grid(LEN / IT, BATCH);                      // (256, 8)
    attn_kernel<<<grid, 512>>>(out);
}

// round 7
// speedup vs baseline: 1.1301x; 1.1301x over previous
#include <cuda_runtime.h>
#include <cuda_fp16.h>

#define BATCH 8
#define LEN   2048
#define EMB   512
#define NQ    8
#define IT    16     // i-rows per attn block
#define JPT   4      // j-columns per thread

// scratch for rot = x @ rotation : (8, 2048, 8) fp32 = 512 KB (L2-resident)
__device__ float g_rot[BATCH * LEN * NQ];

__device__ __forceinline__ float tanh_fast(float x) {
    float y;
    asm("tanh.approx.f32 %0, %1;" : "=f"(y) : "f"(x));
    return y;
}

// ---------------------------------------------------------------------------
// Kernel 1: rot[b,l,q] = sum_e x[b,l,e] * rotation[e,q]
// 1024 blocks x 256 threads. Each warp computes 2 rows; all 8 row-loads
// (LDG.128) issued up-front (MLP=8). Swap-butterfly reduction (17 SHFL),
// lanes 0..15 store coalesced. (R5 form: no .cs hints — R6 showed they hurt.)
// ---------------------------------------------------------------------------
__global__ __launch_bounds__(256) void rot_kernel(const float* __restrict__ x,
                                                  const float* __restrict__ rotation)
{
    __shared__ float4 srotT4[NQ][EMB / 4];   // transposed rotation, 16 KB
    const int tid = threadIdx.x;

    float* srot = reinterpret_cast<float*>(srotT4);
    for (int idx = tid; idx < EMB * NQ; idx += 256) {
        int e = idx >> 3;
        int q = idx & 7;
        srot[q * EMB + e] = rotation[idx];
    }
    __syncthreads();

    const int warp = tid >> 5;
    const int lane = tid & 31;
    const int row0 = (blockIdx.x * 8 + warp) * 2;   // 2 rows per warp

    float4 xv[2][4];
#pragma unroll
    for (int r = 0; r < 2; r++)
#pragma unroll
        for (int k = 0; k < 4; k++)
            xv[r][k] = reinterpret_cast<const float4*>(
                x + (size_t)(row0 + r) * EMB)[k * 32 + lane];

    float a[16];   // a[o], o = r*8+q
#pragma unroll
    for (int o = 0; o < 16; o++) a[o] = 0.0f;

#pragma unroll
    for (int k = 0; k < 4; k++) {
#pragma unroll
        for (int q = 0; q < NQ; q++) {
            const float4 rq = srotT4[q][k * 32 + lane];
#pragma unroll
            for (int r = 0; r < 2; r++) {
                float& acc = a[r * 8 + q];
                acc = fmaf(xv[r][k].x, rq.x, acc);
                acc = fmaf(xv[r][k].y, rq.y, acc);
                acc = fmaf(xv[r][k].z, rq.z, acc);
                acc = fmaf(xv[r][k].w, rq.w, acc);
            }
        }
    }

#pragma unroll
    for (int off = 8; off >= 1; off >>= 1) {
#pragma unroll
        for (int t = 0; t < 8; t++) {
            if (t < off) {
                const bool hi = (lane & off) != 0;
                const float give = hi ? a[t] : a[t + off];
                const float keep = hi ? a[t + off] : a[t];
                a[t] = keep + __shfl_xor_sync(0xffffffffu, give, off);
            }
        }
    }
    a[0] += __shfl_xor_sync(0xffffffffu, a[0], 16);

    if (lane < 16)
        g_rot[(size_t)row0 * NQ + lane] = a[0];
}

// ---------------------------------------------------------------------------
// Kernel 2: scores[b,i,j] = sigmoid(rot_i . rot_j) / row_sum
//   sigmoid(s) = 0.5 + 0.5*tanh(0.5*s)   (0.5 folded into qi)
//   row_sum    = 1024 + 0.5*sum_j tanh   ->  out = fmaf(t, h, h), h = 0.5/row_sum
// Block = 512 threads (16 warps), IT=16 i-rows, JPT=4, grid (128, 8) = 1024
// blocks. Halved j-read traffic vs IT=8: L2 total ~200 MB (floor ~18 us).
// tanh values compressed to half2 (exact at +-1 saturation); fp32 row sums.
// ---------------------------------------------------------------------------
__global__ __launch_bounds__(512, 1) void attn_kernel(float* __restrict__ out)
{
    const int b    = blockIdx.y;
    const int i0   = blockIdx.x * IT;
    const int tid  = threadIdx.x;
    const int warp = tid >> 5;
    const int lane = tid & 31;

    __shared__ float s_q[IT * NQ];      // 0.5 * qi rows, 128 floats
    __shared__ float s_part[IT][16];
    __shared__ float s_h[IT];

    if (tid < IT * NQ)
        s_q[tid] = 0.5f * g_rot[((size_t)b * LEN + i0) * NQ + tid];

    // this thread's 4 j-rows (128B contiguous): 8 x LDG.128, MLP = 8
    const float4* rj = reinterpret_cast<const float4*>(
        &g_rot[((size_t)b * LEN + tid * JPT) * NQ]);
    float4 v0[JPT], v1[JPT];
#pragma unroll
    for (int r = 0; r < JPT; r++) {
        v0[r] = __ldg(rj + r * 2 + 0);
        v1[r] = __ldg(rj + r * 2 + 1);
    }

    __syncthreads();

    __half2 th[IT][2];      // tanh values, pairs (t0,t1) (t2,t3)
    float   a[IT];          // fp32 partial row sums
    const float4* sq4 = reinterpret_cast<const float4*>(s_q);

#pragma unroll
    for (int i = 0; i < IT; i++) {
        const float4 q0 = sq4[i * 2 + 0];   // broadcast LDS.128
        const float4 q1 = sq4[i * 2 + 1];
        float t[JPT];
#pragma unroll
        for (int r = 0; r < JPT; r++) {
            float s0 = v0[r].x * q0.x;
            float s1 = v1[r].x * q1.x;
            s0 = fmaf(v0[r].y, q0.y, s0);
            s1 = fmaf(v1[r].y, q1.y, s1);
            s0 = fmaf(v0[r].z, q0.z, s0);
            s1 = fmaf(v1[r].z, q1.z, s1);
            s0 = fmaf(v0[r].w, q0.w, s0);
            s1 = fmaf(v1[r].w, q1.w, s1);
            t[r] = tanh_fast(s0 + s1);
        }
        a[i] = (t[0] + t[1]) + (t[2] + t[3]);
        th[i][0] = __floats2half2_rn(t[0], t[1]);
        th[i][1] = __floats2half2_rn(t[2], t[3]);
    }

    // swap-butterfly warp reduce of 16 row partials: stages 8,4,2,1 then 16.
    // After: lane l holds this warp's partial for row (l & 15).
#pragma unroll
    for (int off = 8; off >= 1; off >>= 1) {
#pragma unroll
        for (int t = 0; t < 8; t++) {
            if (t < off) {
                const bool hi = (lane & off) != 0;
                const float give = hi ? a[t] : a[t + off];
                const float keep = hi ? a[t + off] : a[t];
                a[t] = keep + __shfl_xor_sync(0xffffffffu, give, off);
            }
        }
    }
    a[0] += __shfl_xor_sync(0xffffffffu, a[0], 16);

    if (lane < IT)
        s_part[lane][warp] = a[0];

    __syncthreads();

    // second level: warp w (16 warps) reduces row w's 16 warp-partials
    {
        float p = (lane < 16) ? s_part[warp][lane] : 0.0f;
#pragma unroll
        for (int off = 8; off >= 1; off >>= 1)
            p += __shfl_xor_sync(0xffffffffu, p, off);
        if (lane == 0)
            s_h[warp] = __fdividef(0.5f, fmaf(0.5f, p, 1024.0f));
    }
    __syncthreads();

    float4* obase = reinterpret_cast<float4*>(
        out + ((size_t)(b * LEN + i0)) * LEN) + tid;
#pragma unroll
    for (int i = 0; i < IT; i++) {
        const float h = s_h[i];
        const float2 lo = __half22float2(th[i][0]);
        const float2 hi = __half22float2(th[i][1]);
        float4 o;
        o.x = fmaf(lo.x, h, h);
        o.y = fmaf(lo.y, h, h);
        o.z = fmaf(hi.x, h, h);
        o.w = fmaf(hi.y, h, h);
        __stcs(obase, o);                 // evict-first streaming STG.128
        obase += LEN / 4;
    }
}

extern "C" void kernel_launch(void* const* d_in, const int* in_sizes, int n_in,
                              void* d_out, int out_size)
{
    const float* x        = (const float*)d_in[0];   // (8, 2048, 512)
    const float* rotation = (const float*)d_in[1];   // (512, 8)
    float* out = (float*)d_out;                      // (8, 2048, 2048)

    rot_kernel<<<1024, 256>>>(x, rotation);

    dim3 grid(LEN / IT, BATCH);                      // (128, 8)
    attn_kernel<<<grid, 512>>>(out);
}

// round 8
// speedup vs baseline: 1.2846x; 1.1368x over previous
#include <cuda_runtime.h>
#include <cuda_fp16.h>

#define BATCH 8
#define LEN   2048
#define EMB   512
#define NQ    8
#define IT    16     // i-rows per attn block
#define JPT   4      // j-columns per thread
#define THR   512    // attn block size

// dynamic smem for the tanh buffer: THR*IT*8 bytes = 64 KB
#define SMEM_TH_BYTES (THR * IT * 8)

// scratch for rot = x @ rotation : (8, 2048, 8) fp32 = 512 KB (L2-resident)
__device__ float g_rot[BATCH * LEN * NQ];

__device__ __forceinline__ float tanh_fast(float x) {
    float y;
    asm("tanh.approx.f32 %0, %1;" : "=f"(y) : "f"(x));
    return y;
}
__device__ __forceinline__ unsigned int h2_to_u(__half2 h) {
    return *reinterpret_cast<unsigned int*>(&h);
}
__device__ __forceinline__ __half2 u_to_h2(unsigned int u) {
    return *reinterpret_cast<__half2*>(&u);
}

// ---------------------------------------------------------------------------
// Kernel 1: rot[b,l,q] = sum_e x[b,l,e] * rotation[e,q]
// 1024 blocks x 256 threads. Each warp computes 2 rows; all 8 row-loads
// (LDG.128) issued up-front (MLP=8). Swap-butterfly reduction (17 SHFL),
// lanes 0..15 store coalesced.
// ---------------------------------------------------------------------------
__global__ __launch_bounds__(256) void rot_kernel(const float* __restrict__ x,
                                                  const float* __restrict__ rotation)
{
    __shared__ float4 srotT4[NQ][EMB / 4];   // transposed rotation, 16 KB
    const int tid = threadIdx.x;

    float* srot = reinterpret_cast<float*>(srotT4);
    for (int idx = tid; idx < EMB * NQ; idx += 256) {
        int e = idx >> 3;
        int q = idx & 7;
        srot[q * EMB + e] = rotation[idx];
    }
    __syncthreads();

    const int warp = tid >> 5;
    const int lane = tid & 31;
    const int row0 = (blockIdx.x * 8 + warp) * 2;   // 2 rows per warp

    float4 xv[2][4];
#pragma unroll
    for (int r = 0; r < 2; r++)
#pragma unroll
        for (int k = 0; k < 4; k++)
            xv[r][k] = reinterpret_cast<const float4*>(
                x + (size_t)(row0 + r) * EMB)[k * 32 + lane];

    float a[16];   // a[o], o = r*8+q
#pragma unroll
    for (int o = 0; o < 16; o++) a[o] = 0.0f;

#pragma unroll
    for (int k = 0; k < 4; k++) {
#pragma unroll
        for (int q = 0; q < NQ; q++) {
            const float4 rq = srotT4[q][k * 32 + lane];
#pragma unroll
            for (int r = 0; r < 2; r++) {
                float& acc = a[r * 8 + q];
                acc = fmaf(xv[r][k].x, rq.x, acc);
                acc = fmaf(xv[r][k].y, rq.y, acc);
                acc = fmaf(xv[r][k].z, rq.z, acc);
                acc = fmaf(xv[r][k].w, rq.w, acc);
            }
        }
    }

#pragma unroll
    for (int off = 8; off >= 1; off >>= 1) {
#pragma unroll
        for (int t = 0; t < 8; t++) {
            if (t < off) {
                const bool hi = (lane & off) != 0;
                const float give = hi ? a[t] : a[t + off];
                const float keep = hi ? a[t + off] : a[t];
                a[t] = keep + __shfl_xor_sync(0xffffffffu, give, off);
            }
        }
    }
    a[0] += __shfl_xor_sync(0xffffffffu, a[0], 16);

    if (lane < 16)
        g_rot[(size_t)row0 * NQ + lane] = a[0];
}

// swap-butterfly reduce of 8 per-row partials within a warp.
// After: every lane holds the full-warp sum for row (lane & 7).
__device__ __forceinline__ void butterfly8(float a[8], int lane) {
#pragma unroll
    for (int off = 4; off >= 1; off >>= 1) {
#pragma unroll
        for (int t = 0; t < 4; t++) {
            if (t < off) {
                const bool hi = (lane & off) != 0;
                const float give = hi ? a[t] : a[t + off];
                const float keep = hi ? a[t + off] : a[t];
                a[t] = keep + __shfl_xor_sync(0xffffffffu, give, off);
            }
        }
    }
    a[0] += __shfl_xor_sync(0xffffffffu, a[0], 8);
    a[0] += __shfl_xor_sync(0xffffffffu, a[0], 16);
}

// ---------------------------------------------------------------------------
// Kernel 2: scores[b,i,j] = sigmoid(rot_i . rot_j) / row_sum
//   sigmoid(s) = 0.5 + 0.5*tanh(0.5*s)   (0.5 folded into qi)
//   row_sum    = 1024 + 0.5*sum_j tanh   ->  out = fmaf(t, h, h), h = 0.5/row_sum
// Block = 512 threads, IT=16, JPT=4, grid (128, 8). The per-thread tanh
// buffer lives in 64 KB dynamic smem (uint2 per (i,thread), [i][tid] layout,
// conflict-free STS.64/LDS.64) instead of 32 registers, and the row-partial
// reduction runs in two 8-row batches (live a[8]), so regs fit 64 ->
// 2 blocks/SM co-resident, overlapping each other's barrier phases.
// ---------------------------------------------------------------------------
__global__ __launch_bounds__(THR, 2) void attn_kernel(float* __restrict__ out)
{
    extern __shared__ uint2 s_th[];     // [i*THR + tid]  (64 KB)
    __shared__ float s_q[IT * NQ];      // 0.5 * qi rows
    __shared__ float s_part[IT][16];
    __shared__ float s_h[IT];

    const int b    = blockIdx.y;
    const int i0   = blockIdx.x * IT;
    const int tid  = threadIdx.x;
    const int warp = tid >> 5;
    const int lane = tid & 31;

    if (tid < IT * NQ)
        s_q[tid] = 0.5f * g_rot[((size_t)b * LEN + i0) * NQ + tid];

    // this thread's 4 j-rows (128B contiguous): 8 x LDG.128, MLP = 8
    const float4* rj = reinterpret_cast<const float4*>(
        &g_rot[((size_t)b * LEN + tid * JPT) * NQ]);
    float4 v0[JPT], v1[JPT];
#pragma unroll
    for (int r = 0; r < JPT; r++) {
        v0[r] = __ldg(rj + r * 2 + 0);
        v1[r] = __ldg(rj + r * 2 + 1);
    }

    __syncthreads();

    const float4* sq4 = reinterpret_cast<const float4*>(s_q);
    float a[8];

#pragma unroll
    for (int half = 0; half < 2; half++) {
#pragma unroll
        for (int u = 0; u < 8; u++) {
            const int i = half * 8 + u;
            const float4 q0 = sq4[i * 2 + 0];   // broadcast LDS.128
            const float4 q1 = sq4[i * 2 + 1];
            float t[JPT];
#pragma unroll
            for (int r = 0; r < JPT; r++) {
                float s0 = v0[r].x * q0.x;
                float s1 = v1[r].x * q1.x;
                s0 = fmaf(v0[r].y, q0.y, s0);
                s1 = fmaf(v1[r].y, q1.y, s1);
                s0 = fmaf(v0[r].z, q0.z, s0);
                s1 = fmaf(v1[r].z, q1.z, s1);
                s0 = fmaf(v0[r].w, q0.w, s0);
                s1 = fmaf(v1[r].w, q1.w, s1);
                t[r] = tanh_fast(s0 + s1);
            }
            a[u] = (t[0] + t[1]) + (t[2] + t[3]);
            uint2 u2;
            u2.x = h2_to_u(__floats2half2_rn(t[0], t[1]));
            u2.y = h2_to_u(__floats2half2_rn(t[2], t[3]));
            s_th[i * THR + tid] = u2;           // STS.64, conflict-free
        }
        butterfly8(a, lane);
        if (lane < 8)
            s_part[half * 8 + lane][warp] = a[0];
    }

    __syncthreads();

    // second level: warp w (16 warps) reduces row w's 16 warp-partials
    {
        float p = (lane < 16) ? s_part[warp][lane] : 0.0f;
#pragma unroll
        for (int off = 8; off >= 1; off >>= 1)
            p += __shfl_xor_sync(0xffffffffu, p, off);
        if (lane == 0)
            s_h[warp] = __fdividef(0.5f, fmaf(0.5f, p, 1024.0f));
    }
    __syncthreads();

    float4* obase = reinterpret_cast<float4*>(
        out + ((size_t)(b * LEN + i0)) * LEN) + tid;
#pragma unroll
    for (int i = 0; i < IT; i++) {
        const float h = s_h[i];
        const uint2 u2 = s_th[i * THR + tid];   // LDS.64, conflict-free
        const float2 lo = __half22float2(u_to_h2(u2.x));
        const float2 hi = __half22float2(u_to_h2(u2.y));
        float4 o;
        o.x = fmaf(lo.x, h, h);
        o.y = fmaf(lo.y, h, h);
        o.z = fmaf(hi.x, h, h);
        o.w = fmaf(hi.y, h, h);
        __stcs(obase, o);                       // evict-first streaming STG.128
        obase += LEN / 4;
    }
}

extern "C" void kernel_launch(void* const* d_in, const int* in_sizes, int n_in,
                              void* d_out, int out_size)
{
    const float* x        = (const float*)d_in[0];   // (8, 2048, 512)
    const float* rotation = (const float*)d_in[1];   // (512, 8)
    float* out = (float*)d_out;                      // (8, 2048, 2048)

    // opt-in to >48KB dynamic smem (idempotent; not a stream op, capture-safe)
    static int smem_set = 0;
    if (!smem_set) {
        cudaFuncSetAttribute(attn_kernel,
                             cudaFuncAttributeMaxDynamicSharedMemorySize,
                             SMEM_TH_BYTES);
        smem_set = 1;
    }

    rot_kernel<<<1024, 256>>>(x, rotation);

    dim3 grid(LEN / IT, BATCH);                      // (128, 8)
    attn_kernel<<<grid, THR, SMEM_TH_BYTES>>>(out);
}